// round 3
// baseline (speedup 1.0000x reference)
#include <cuda_runtime.h>
#include <cuda_bf16.h>
#include <cstdint>

#define M_DIM 16384
#define N_DIM 1000
#define N_PAD 1024
#define K_DIM 2048
#define BM 128
#define BN 128
#define BK 64
#define NKT (K_DIM / BK)   // 32 k-tiles
#define NSTAGE 3
#define STG_STRIDE 32768u  // A 16KB + B 16KB per stage
#define EPS_D2 1e-12f

// ---- scratch (allocation-free: __device__ globals) ----
__device__ __align__(256) __nv_bfloat16 g_xb[(size_t)M_DIM * K_DIM];
__device__ __align__(256) __nv_bfloat16 g_wb[(size_t)N_PAD * K_DIM];
__device__ float g_x2[M_DIM];
__device__ float g_w2[N_PAD];

// ---------------- helpers ----------------
__device__ __forceinline__ float block_reduce_sum(float s) {
    #pragma unroll
    for (int o = 16; o > 0; o >>= 1) s += __shfl_xor_sync(0xffffffffu, s, o);
    __shared__ float red[8];
    if ((threadIdx.x & 31) == 0) red[threadIdx.x >> 5] = s;
    __syncthreads();
    if (threadIdx.x < 8) {
        s = red[threadIdx.x];
        #pragma unroll
        for (int o = 4; o > 0; o >>= 1) s += __shfl_xor_sync(0xffu, s, o);
    }
    return s;  // valid on thread 0
}

__device__ __forceinline__ void cp_async16(uint32_t smem, const void* gmem) {
    asm volatile("cp.async.cg.shared.global [%0], [%1], 16;\n" :: "r"(smem), "l"(gmem));
}
__device__ __forceinline__ void cp_commit() {
    asm volatile("cp.async.commit_group;\n");
}
template <int Nrem>
__device__ __forceinline__ void cp_wait() {
    asm volatile("cp.async.wait_group %0;\n" :: "n"(Nrem));
}
__device__ __forceinline__ void ldsm_x4(uint32_t& r0, uint32_t& r1, uint32_t& r2, uint32_t& r3,
                                        uint32_t addr) {
    asm volatile("ldmatrix.sync.aligned.m8n8.x4.shared.b16 {%0,%1,%2,%3}, [%4];\n"
                 : "=r"(r0), "=r"(r1), "=r"(r2), "=r"(r3) : "r"(addr));
}
__device__ __forceinline__ void mma16816(float* c,
                                         uint32_t a0, uint32_t a1, uint32_t a2, uint32_t a3,
                                         uint32_t b0, uint32_t b1) {
    asm volatile("mma.sync.aligned.m16n8k16.row.col.f32.bf16.bf16.f32 "
                 "{%0,%1,%2,%3}, {%4,%5,%6,%7}, {%8,%9}, {%0,%1,%2,%3};\n"
                 : "+f"(c[0]), "+f"(c[1]), "+f"(c[2]), "+f"(c[3])
                 : "r"(a0), "r"(a1), "r"(a2), "r"(a3), "r"(b0), "r"(b1));
}

// ---------------- conversion kernels ----------------
__global__ void convert_x_kernel(const float* __restrict__ src) {
    const int row = blockIdx.x;
    const float4* sr = reinterpret_cast<const float4*>(src + (size_t)row * K_DIM);
    __nv_bfloat162* dr = reinterpret_cast<__nv_bfloat162*>(g_xb + (size_t)row * K_DIM);
    float s = 0.f;
    for (int i = threadIdx.x; i < K_DIM / 4; i += 256) {
        float4 v = sr[i];
        s += v.x * v.x + v.y * v.y + v.z * v.z + v.w * v.w;
        dr[2 * i]     = __floats2bfloat162_rn(v.x, v.y);
        dr[2 * i + 1] = __floats2bfloat162_rn(v.z, v.w);
    }
    s = block_reduce_sum(s);
    if (threadIdx.x == 0) g_x2[row] = s;
}

__global__ void convert_w_kernel(const float* __restrict__ src) {
    const int row = blockIdx.x;
    __nv_bfloat162* dr = reinterpret_cast<__nv_bfloat162*>(g_wb + (size_t)row * K_DIM);
    float s = 0.f;
    if (row < N_DIM) {
        const float4* sr = reinterpret_cast<const float4*>(src + (size_t)row * K_DIM);
        for (int i = threadIdx.x; i < K_DIM / 4; i += 256) {
            float4 v = sr[i];
            s += v.x * v.x + v.y * v.y + v.z * v.z + v.w * v.w;
            dr[2 * i]     = __floats2bfloat162_rn(v.x, v.y);
            dr[2 * i + 1] = __floats2bfloat162_rn(v.z, v.w);
        }
    } else {
        const __nv_bfloat162 z = __floats2bfloat162_rn(0.f, 0.f);
        for (int i = threadIdx.x; i < K_DIM / 4; i += 256) {
            dr[2 * i] = z; dr[2 * i + 1] = z;
        }
    }
    s = block_reduce_sum(s);
    if (threadIdx.x == 0) g_w2[row] = s;
}

// ---------------- GEMM + fused distance epilogue ----------------
// CTA tile 128x128x64, 4 warps (2x2), warp tile 64x64.
// 3-stage cp.async pipeline, 32KB/stage, 96KB smem, 2 CTAs/SM.
// Swizzle: row = 8 chunks of 16B; chunk' = chunk ^ (row & 7).

__device__ __forceinline__ void load_stage(uint32_t sbase, int buf, int bm, int bn,
                                           int kt, int tid) {
    const int k0 = kt * BK;
    const uint32_t sA = sbase + (uint32_t)buf * STG_STRIDE;
    const uint32_t sB = sA + 16384u;
    #pragma unroll
    for (int i = 0; i < 8; ++i) {
        int ch = tid + (i << 7);
        int r = ch >> 3, c = ch & 7;
        cp_async16(sA + (uint32_t)(((r << 3) | (c ^ (r & 7))) << 4),
                   g_xb + (size_t)(bm + r) * K_DIM + k0 + (c << 3));
    }
    #pragma unroll
    for (int i = 0; i < 8; ++i) {
        int ch = tid + (i << 7);
        int r = ch >> 3, c = ch & 7;
        cp_async16(sB + (uint32_t)(((r << 3) | (c ^ (r & 7))) << 4),
                   g_wb + (size_t)(bn + r) * K_DIM + k0 + (c << 3));
    }
    cp_commit();
}

__global__ void __launch_bounds__(128, 2)
gemm_dist_kernel(const float* __restrict__ scales, float* __restrict__ out) {
    extern __shared__ __align__(128) char smem[];
    const uint32_t sbase = (uint32_t)__cvta_generic_to_shared(smem);

    const int tid  = threadIdx.x;
    const int lane = tid & 31;
    const int wid  = tid >> 5;
    const int wm   = wid & 1;   // 0..1 -> 64 rows each
    const int wn   = wid >> 1;  // 0..1 -> 64 cols each
    const int bm   = blockIdx.y * BM;
    const int bn   = blockIdx.x * BN;

    float acc[4][8][4];
    #pragma unroll
    for (int i = 0; i < 4; ++i)
        #pragma unroll
        for (int j = 0; j < 8; ++j)
            #pragma unroll
            for (int k = 0; k < 4; ++k) acc[i][j][k] = 0.f;

    load_stage(sbase, 0, bm, bn, 0, tid);
    load_stage(sbase, 1, bm, bn, 1, tid);

    #pragma unroll 1
    for (int kt = 0; kt < NKT; ++kt) {
        const int buf = kt % NSTAGE;
        cp_wait<1>();
        __syncthreads();

        // prefetch stage kt+2 (buffer (kt+2)%3 was consumed in iter kt-1;
        // the barrier above guarantees all warps are past it)
        if (kt + 2 < NKT) load_stage(sbase, (kt + 2) % NSTAGE, bm, bn, kt + 2, tid);
        else              cp_commit();  // keep group count in sync for cp_wait<1>

        const uint32_t sA = sbase + (uint32_t)buf * STG_STRIDE;
        const uint32_t sB = sA + 16384u;

        #pragma unroll
        for (int kk = 0; kk < 4; ++kk) {   // 4 x k16 per BK=64
            uint32_t a[4][4], b[4][4];
            #pragma unroll
            for (int mt = 0; mt < 4; ++mt) {
                int r = wm * 64 + mt * 16 + (lane & 15);
                int c = kk * 2 + (lane >> 4);
                ldsm_x4(a[mt][0], a[mt][1], a[mt][2], a[mt][3],
                        sA + (uint32_t)(((r << 3) | (c ^ (r & 7))) << 4));
            }
            #pragma unroll
            for (int nb = 0; nb < 4; ++nb) {
                int r = wn * 64 + nb * 16 + (lane & 7) + ((lane & 16) >> 1);
                int c = kk * 2 + ((lane >> 3) & 1);
                ldsm_x4(b[nb][0], b[nb][1], b[nb][2], b[nb][3],
                        sB + (uint32_t)(((r << 3) | (c ^ (r & 7))) << 4));
            }
            #pragma unroll
            for (int mt = 0; mt < 4; ++mt)
                #pragma unroll
                for (int nt = 0; nt < 8; ++nt)
                    mma16816(acc[mt][nt],
                             a[mt][0], a[mt][1], a[mt][2], a[mt][3],
                             b[nt >> 1][(nt & 1) * 2], b[nt >> 1][(nt & 1) * 2 + 1]);
        }
        __syncthreads();
    }

    // Epilogue: out = -s * sqrt(max(x2 + w2 - 2*cross, eps))
    const float sc = __ldg(scales);
    #pragma unroll
    for (int mt = 0; mt < 4; ++mt) {
        const int row = bm + wm * 64 + mt * 16 + (lane >> 2);
        const float x2a = g_x2[row];
        const float x2b = g_x2[row + 8];
        #pragma unroll
        for (int nt = 0; nt < 8; ++nt) {
            const int col = bn + wn * 64 + nt * 8 + ((lane & 3) << 1);
            if (col < N_DIM) {   // col even, N_DIM even -> col+1 also valid
                const float w2a = g_w2[col];
                const float w2b = g_w2[col + 1];
                float2 v;
                v.x = -sc * sqrtf(fmaxf(x2a + w2a - 2.f * acc[mt][nt][0], EPS_D2));
                v.y = -sc * sqrtf(fmaxf(x2a + w2b - 2.f * acc[mt][nt][1], EPS_D2));
                *reinterpret_cast<float2*>(out + (size_t)row * N_DIM + col) = v;
                v.x = -sc * sqrtf(fmaxf(x2b + w2a - 2.f * acc[mt][nt][2], EPS_D2));
                v.y = -sc * sqrtf(fmaxf(x2b + w2b - 2.f * acc[mt][nt][3], EPS_D2));
                *reinterpret_cast<float2*>(out + (size_t)(row + 8) * N_DIM + col) = v;
            }
        }
    }
}

// ---------------- launch ----------------
extern "C" void kernel_launch(void* const* d_in, const int* in_sizes, int n_in,
                              void* d_out, int out_size) {
    const float* x      = (const float*)d_in[0];  // [16384, 2048]
    const float* w      = (const float*)d_in[1];  // [1000, 2048]
    const float* scales = (const float*)d_in[2];  // [1]
    float* out          = (float*)d_out;          // [16384, 1000]

    convert_x_kernel<<<M_DIM, 256>>>(x);
    convert_w_kernel<<<N_PAD, 256>>>(w);

    cudaFuncSetAttribute(gemm_dist_kernel,
                         cudaFuncAttributeMaxDynamicSharedMemorySize, NSTAGE * STG_STRIDE);
    dim3 grid(N_PAD / BN, M_DIM / BM);  // (8, 128) = 1024 CTAs
    gemm_dist_kernel<<<grid, 128, NSTAGE * STG_STRIDE>>>(scales, out);
}

// round 4
// speedup vs baseline: 1.0777x; 1.0777x over previous
#include <cuda_runtime.h>
#include <cuda_bf16.h>
#include <cstdint>

#define M_DIM 16384
#define N_DIM 1000
#define N_PAD 1024
#define K_DIM 2048
#define BM 128
#define BN 128
#define BK 64
#define NKT (K_DIM / BK)   // 32 k-tiles
#define NSTAGE 3
#define STG_STRIDE 32768u  // A 16KB + B 16KB per stage
#define EPS_D2 1e-12f

// ---- scratch (allocation-free: __device__ globals) ----
__device__ __align__(256) __nv_bfloat16 g_xb[(size_t)M_DIM * K_DIM];
__device__ __align__(256) __nv_bfloat16 g_wb[(size_t)N_PAD * K_DIM];
__device__ float g_x2[M_DIM];
__device__ float g_w2[N_PAD];

// ---------------- helpers ----------------
__device__ __forceinline__ float block_reduce_sum(float s) {
    #pragma unroll
    for (int o = 16; o > 0; o >>= 1) s += __shfl_xor_sync(0xffffffffu, s, o);
    __shared__ float red[8];
    if ((threadIdx.x & 31) == 0) red[threadIdx.x >> 5] = s;
    __syncthreads();
    if (threadIdx.x < 8) {
        s = red[threadIdx.x];
        #pragma unroll
        for (int o = 4; o > 0; o >>= 1) s += __shfl_xor_sync(0xffu, s, o);
    }
    return s;  // valid on thread 0
}

__device__ __forceinline__ void cp_async16(uint32_t smem, const void* gmem) {
    asm volatile("cp.async.cg.shared.global [%0], [%1], 16;\n" :: "r"(smem), "l"(gmem));
}
__device__ __forceinline__ void cp_commit() {
    asm volatile("cp.async.commit_group;\n");
}
template <int Nrem>
__device__ __forceinline__ void cp_wait() {
    asm volatile("cp.async.wait_group %0;\n" :: "n"(Nrem));
}
__device__ __forceinline__ void ldsm_x4(uint32_t& r0, uint32_t& r1, uint32_t& r2, uint32_t& r3,
                                        uint32_t addr) {
    asm volatile("ldmatrix.sync.aligned.m8n8.x4.shared.b16 {%0,%1,%2,%3}, [%4];\n"
                 : "=r"(r0), "=r"(r1), "=r"(r2), "=r"(r3) : "r"(addr));
}
__device__ __forceinline__ void mma16816(float* c,
                                         uint32_t a0, uint32_t a1, uint32_t a2, uint32_t a3,
                                         uint32_t b0, uint32_t b1) {
    asm volatile("mma.sync.aligned.m16n8k16.row.col.f32.bf16.bf16.f32 "
                 "{%0,%1,%2,%3}, {%4,%5,%6,%7}, {%8,%9}, {%0,%1,%2,%3};\n"
                 : "+f"(c[0]), "+f"(c[1]), "+f"(c[2]), "+f"(c[3])
                 : "r"(a0), "r"(a1), "r"(a2), "r"(a3), "r"(b0), "r"(b1));
}

// ---------------- conversion kernels ----------------
__global__ void convert_x_kernel(const float* __restrict__ src) {
    const int row = blockIdx.x;
    const float4* sr = reinterpret_cast<const float4*>(src + (size_t)row * K_DIM);
    __nv_bfloat162* dr = reinterpret_cast<__nv_bfloat162*>(g_xb + (size_t)row * K_DIM);
    float s = 0.f;
    for (int i = threadIdx.x; i < K_DIM / 4; i += 256) {
        float4 v = sr[i];
        s += v.x * v.x + v.y * v.y + v.z * v.z + v.w * v.w;
        dr[2 * i]     = __floats2bfloat162_rn(v.x, v.y);
        dr[2 * i + 1] = __floats2bfloat162_rn(v.z, v.w);
    }
    s = block_reduce_sum(s);
    if (threadIdx.x == 0) g_x2[row] = s;
}

__global__ void convert_w_kernel(const float* __restrict__ src) {
    const int row = blockIdx.x;
    __nv_bfloat162* dr = reinterpret_cast<__nv_bfloat162*>(g_wb + (size_t)row * K_DIM);
    float s = 0.f;
    if (row < N_DIM) {
        const float4* sr = reinterpret_cast<const float4*>(src + (size_t)row * K_DIM);
        for (int i = threadIdx.x; i < K_DIM / 4; i += 256) {
            float4 v = sr[i];
            s += v.x * v.x + v.y * v.y + v.z * v.z + v.w * v.w;
            dr[2 * i]     = __floats2bfloat162_rn(v.x, v.y);
            dr[2 * i + 1] = __floats2bfloat162_rn(v.z, v.w);
        }
    } else {
        const __nv_bfloat162 z = __floats2bfloat162_rn(0.f, 0.f);
        for (int i = threadIdx.x; i < K_DIM / 4; i += 256) {
            dr[2 * i] = z; dr[2 * i + 1] = z;
        }
    }
    s = block_reduce_sum(s);
    if (threadIdx.x == 0) g_w2[row] = s;
}

// ---------------- GEMM + fused distance epilogue ----------------
// CTA tile 128x128x64, 4 warps (2x2), warp tile 64x64.
// 3-stage cp.async pipeline, software-pipelined fragments (ldsm one kk ahead),
// single __syncthreads per iteration. 96KB smem, 2 CTAs/SM, ~215 regs/thread.
// Swizzle: row = 8 chunks of 16B; chunk' = chunk ^ (row & 7).

__device__ __forceinline__ void load_stage(uint32_t sbase, int buf, int bm, int bn,
                                           int kt, int tid) {
    const int k0 = kt * BK;
    const uint32_t sA = sbase + (uint32_t)buf * STG_STRIDE;
    const uint32_t sB = sA + 16384u;
    #pragma unroll
    for (int i = 0; i < 8; ++i) {
        int ch = tid + (i << 7);
        int r = ch >> 3, c = ch & 7;
        cp_async16(sA + (uint32_t)(((r << 3) | (c ^ (r & 7))) << 4),
                   g_xb + (size_t)(bm + r) * K_DIM + k0 + (c << 3));
    }
    #pragma unroll
    for (int i = 0; i < 8; ++i) {
        int ch = tid + (i << 7);
        int r = ch >> 3, c = ch & 7;
        cp_async16(sB + (uint32_t)(((r << 3) | (c ^ (r & 7))) << 4),
                   g_wb + (size_t)(bn + r) * K_DIM + k0 + (c << 3));
    }
    cp_commit();
}

__device__ __forceinline__ void load_frags(uint32_t a[4][4], uint32_t b[4][4],
                                           uint32_t sA, uint32_t sB, int kk,
                                           int lane, int wm, int wn) {
    #pragma unroll
    for (int mt = 0; mt < 4; ++mt) {
        int r = wm * 64 + mt * 16 + (lane & 15);
        int c = kk * 2 + (lane >> 4);
        ldsm_x4(a[mt][0], a[mt][1], a[mt][2], a[mt][3],
                sA + (uint32_t)(((r << 3) | (c ^ (r & 7))) << 4));
    }
    #pragma unroll
    for (int nb = 0; nb < 4; ++nb) {
        int r = wn * 64 + nb * 16 + (lane & 7) + ((lane & 16) >> 1);
        int c = kk * 2 + ((lane >> 3) & 1);
        ldsm_x4(b[nb][0], b[nb][1], b[nb][2], b[nb][3],
                sB + (uint32_t)(((r << 3) | (c ^ (r & 7))) << 4));
    }
}

__global__ void __launch_bounds__(128, 2)
gemm_dist_kernel(const float* __restrict__ scales, float* __restrict__ out) {
    extern __shared__ __align__(128) char smem[];
    const uint32_t sbase = (uint32_t)__cvta_generic_to_shared(smem);

    const int tid  = threadIdx.x;
    const int lane = tid & 31;
    const int wid  = tid >> 5;
    const int wm   = wid & 1;   // 0..1 -> 64 rows each
    const int wn   = wid >> 1;  // 0..1 -> 64 cols each
    const int bm   = blockIdx.y * BM;
    const int bn   = blockIdx.x * BN;

    float acc[4][8][4];
    #pragma unroll
    for (int i = 0; i < 4; ++i)
        #pragma unroll
        for (int j = 0; j < 8; ++j)
            #pragma unroll
            for (int k = 0; k < 4; ++k) acc[i][j][k] = 0.f;

    uint32_t a[2][4][4], b[2][4][4];   // double-buffered fragments

    load_stage(sbase, 0, bm, bn, 0, tid);
    load_stage(sbase, 1, bm, bn, 1, tid);

    #pragma unroll 1
    for (int kt = 0; kt < NKT; ++kt) {
        const int buf = kt % NSTAGE;
        cp_wait<1>();
        __syncthreads();   // single barrier per iteration

        // buffer (kt+2)%3 was last read at iter kt-1; the barrier above
        // guarantees every warp is past that read before we overwrite it.
        if (kt + 2 < NKT) load_stage(sbase, (kt + 2) % NSTAGE, bm, bn, kt + 2, tid);
        else              cp_commit();  // keep group count aligned for cp_wait<1>

        const uint32_t sA = sbase + (uint32_t)buf * STG_STRIDE;
        const uint32_t sB = sA + 16384u;

        // software pipeline: frags for kk+1 load while MMAs of kk issue
        load_frags(a[0], b[0], sA, sB, 0, lane, wm, wn);

        #pragma unroll
        for (int kk = 0; kk < 4; ++kk) {
            const int cur = kk & 1;
            if (kk < 3) load_frags(a[cur ^ 1], b[cur ^ 1], sA, sB, kk + 1, lane, wm, wn);
            #pragma unroll
            for (int mt = 0; mt < 4; ++mt)
                #pragma unroll
                for (int nt = 0; nt < 8; ++nt)
                    mma16816(acc[mt][nt],
                             a[cur][mt][0], a[cur][mt][1], a[cur][mt][2], a[cur][mt][3],
                             b[cur][nt >> 1][(nt & 1) * 2], b[cur][nt >> 1][(nt & 1) * 2 + 1]);
        }
    }

    // Epilogue: out = -s * sqrt(max(x2 + w2 - 2*cross, eps))
    const float sc = __ldg(scales);
    #pragma unroll
    for (int mt = 0; mt < 4; ++mt) {
        const int row = bm + wm * 64 + mt * 16 + (lane >> 2);
        const float x2a = g_x2[row];
        const float x2b = g_x2[row + 8];
        #pragma unroll
        for (int nt = 0; nt < 8; ++nt) {
            const int col = bn + wn * 64 + nt * 8 + ((lane & 3) << 1);
            if (col < N_DIM) {   // col even, N_DIM even -> col+1 also valid
                const float w2a = g_w2[col];
                const float w2b = g_w2[col + 1];
                float2 v;
                v.x = -sc * sqrtf(fmaxf(x2a + w2a - 2.f * acc[mt][nt][0], EPS_D2));
                v.y = -sc * sqrtf(fmaxf(x2a + w2b - 2.f * acc[mt][nt][1], EPS_D2));
                *reinterpret_cast<float2*>(out + (size_t)row * N_DIM + col) = v;
                v.x = -sc * sqrtf(fmaxf(x2b + w2a - 2.f * acc[mt][nt][2], EPS_D2));
                v.y = -sc * sqrtf(fmaxf(x2b + w2b - 2.f * acc[mt][nt][3], EPS_D2));
                *reinterpret_cast<float2*>(out + (size_t)(row + 8) * N_DIM + col) = v;
            }
        }
    }
}

// ---------------- launch ----------------
extern "C" void kernel_launch(void* const* d_in, const int* in_sizes, int n_in,
                              void* d_out, int out_size) {
    const float* x      = (const float*)d_in[0];  // [16384, 2048]
    const float* w      = (const float*)d_in[1];  // [1000, 2048]
    const float* scales = (const float*)d_in[2];  // [1]
    float* out          = (float*)d_out;          // [16384, 1000]

    convert_x_kernel<<<M_DIM, 256>>>(x);
    convert_w_kernel<<<N_PAD, 256>>>(w);

    cudaFuncSetAttribute(gemm_dist_kernel,
                         cudaFuncAttributeMaxDynamicSharedMemorySize, NSTAGE * STG_STRIDE);
    dim3 grid(N_PAD / BN, M_DIM / BM);  // (8, 128) = 1024 CTAs
    gemm_dist_kernel<<<grid, 128, NSTAGE * STG_STRIDE>>>(scales, out);
}

// round 5
// speedup vs baseline: 1.2014x; 1.1148x over previous
#include <cuda_runtime.h>
#include <cuda_bf16.h>
#include <cstdint>

#define M_DIM 16384
#define N_DIM 1000
#define N_PAD 1024
#define K_DIM 2048
#define BM 128
#define BN 128
#define BK 64
#define NKT (K_DIM / BK)   // 32 k-tiles
#define NSTAGE 3
#define STG_STRIDE 32768u  // A 16KB + B 16KB per stage
#define EPS_D2 1e-12f

// ---- scratch (allocation-free: __device__ globals) ----
__device__ __align__(256) __nv_bfloat16 g_xb[(size_t)M_DIM * K_DIM];
__device__ __align__(256) __nv_bfloat16 g_wb[(size_t)N_PAD * K_DIM];
__device__ float g_x2[M_DIM];
__device__ float g_w2[N_PAD];

// ---------------- helpers ----------------
__device__ __forceinline__ void cp_async16(uint32_t smem, const void* gmem) {
    asm volatile("cp.async.cg.shared.global [%0], [%1], 16;\n" :: "r"(smem), "l"(gmem));
}
__device__ __forceinline__ void cp_commit() {
    asm volatile("cp.async.commit_group;\n");
}
template <int Nrem>
__device__ __forceinline__ void cp_wait() {
    asm volatile("cp.async.wait_group %0;\n" :: "n"(Nrem));
}
__device__ __forceinline__ void ldsm_x4(uint32_t& r0, uint32_t& r1, uint32_t& r2, uint32_t& r3,
                                        uint32_t addr) {
    asm volatile("ldmatrix.sync.aligned.m8n8.x4.shared.b16 {%0,%1,%2,%3}, [%4];\n"
                 : "=r"(r0), "=r"(r1), "=r"(r2), "=r"(r3) : "r"(addr));
}
__device__ __forceinline__ void mma16816(float* c,
                                         uint32_t a0, uint32_t a1, uint32_t a2, uint32_t a3,
                                         uint32_t b0, uint32_t b1) {
    asm volatile("mma.sync.aligned.m16n8k16.row.col.f32.bf16.bf16.f32 "
                 "{%0,%1,%2,%3}, {%4,%5,%6,%7}, {%8,%9}, {%0,%1,%2,%3};\n"
                 : "+f"(c[0]), "+f"(c[1]), "+f"(c[2]), "+f"(c[3])
                 : "r"(a0), "r"(a1), "r"(a2), "r"(a3), "r"(b0), "r"(b1));
}

// ---------------- conversion kernels (warp-per-row, MLP=16) ----------------
__global__ void convert_x_kernel(const float* __restrict__ src) {
    const int row  = blockIdx.x * 8 + (threadIdx.x >> 5);
    const int lane = threadIdx.x & 31;
    const float4* sr = reinterpret_cast<const float4*>(src + (size_t)row * K_DIM);
    __nv_bfloat162* dr = reinterpret_cast<__nv_bfloat162*>(g_xb + (size_t)row * K_DIM);
    float s = 0.f;
    #pragma unroll
    for (int i = 0; i < 16; ++i) {           // 2048/4 = 512 float4 / 32 lanes
        const int idx = lane + (i << 5);
        float4 v = sr[idx];
        s += v.x * v.x + v.y * v.y + v.z * v.z + v.w * v.w;
        dr[2 * idx]     = __floats2bfloat162_rn(v.x, v.y);
        dr[2 * idx + 1] = __floats2bfloat162_rn(v.z, v.w);
    }
    #pragma unroll
    for (int o = 16; o > 0; o >>= 1) s += __shfl_xor_sync(0xffffffffu, s, o);
    if (lane == 0) g_x2[row] = s;
}

__global__ void convert_w_kernel(const float* __restrict__ src) {
    const int row  = blockIdx.x * 8 + (threadIdx.x >> 5);
    const int lane = threadIdx.x & 31;
    __nv_bfloat162* dr = reinterpret_cast<__nv_bfloat162*>(g_wb + (size_t)row * K_DIM);
    float s = 0.f;
    if (row < N_DIM) {
        const float4* sr = reinterpret_cast<const float4*>(src + (size_t)row * K_DIM);
        #pragma unroll
        for (int i = 0; i < 16; ++i) {
            const int idx = lane + (i << 5);
            float4 v = sr[idx];
            s += v.x * v.x + v.y * v.y + v.z * v.z + v.w * v.w;
            dr[2 * idx]     = __floats2bfloat162_rn(v.x, v.y);
            dr[2 * idx + 1] = __floats2bfloat162_rn(v.z, v.w);
        }
    } else {
        const __nv_bfloat162 z = __floats2bfloat162_rn(0.f, 0.f);
        #pragma unroll
        for (int i = 0; i < 16; ++i) {
            const int idx = lane + (i << 5);
            dr[2 * idx] = z; dr[2 * idx + 1] = z;
        }
    }
    #pragma unroll
    for (int o = 16; o > 0; o >>= 1) s += __shfl_xor_sync(0xffffffffu, s, o);
    if (lane == 0) g_w2[row] = s;
}

// ---------------- GEMM + fused distance epilogue ----------------
// CTA tile 128x128x64, 8 warps (2M x 4N), warp tile 64x32 (R1 config).
// 3-stage cp.async pipeline, single barrier/iter, B-fragment double buffer.
// 96KB smem, 2 CTAs/SM (16 warps/SM), <=128 regs/thread.
// Swizzle: row = 8 chunks of 16B; chunk' = chunk ^ (row & 7).

__device__ __forceinline__ void load_stage(uint32_t sbase, int buf, int bm, int bn,
                                           int kt, int tid) {
    const int k0 = kt * BK;
    const uint32_t sA = sbase + (uint32_t)buf * STG_STRIDE;
    const uint32_t sB = sA + 16384u;
    #pragma unroll
    for (int i = 0; i < 4; ++i) {
        int ch = tid + (i << 8);
        int r = ch >> 3, c = ch & 7;
        cp_async16(sA + (uint32_t)(((r << 3) | (c ^ (r & 7))) << 4),
                   g_xb + (size_t)(bm + r) * K_DIM + k0 + (c << 3));
    }
    #pragma unroll
    for (int i = 0; i < 4; ++i) {
        int ch = tid + (i << 8);
        int r = ch >> 3, c = ch & 7;
        cp_async16(sB + (uint32_t)(((r << 3) | (c ^ (r & 7))) << 4),
                   g_wb + (size_t)(bn + r) * K_DIM + k0 + (c << 3));
    }
    cp_commit();
}

__device__ __forceinline__ void load_b_frags(uint32_t b[2][4], uint32_t sB, int kk,
                                             int lane, int wn) {
    #pragma unroll
    for (int nb = 0; nb < 2; ++nb) {
        int r = wn * 32 + nb * 16 + (lane & 7) + ((lane & 16) >> 1);
        int c = kk * 2 + ((lane >> 3) & 1);
        ldsm_x4(b[nb][0], b[nb][1], b[nb][2], b[nb][3],
                sB + (uint32_t)(((r << 3) | (c ^ (r & 7))) << 4));
    }
}

__global__ void __launch_bounds__(256, 2)
gemm_dist_kernel(const float* __restrict__ scales, float* __restrict__ out) {
    extern __shared__ __align__(128) char smem[];
    const uint32_t sbase = (uint32_t)__cvta_generic_to_shared(smem);

    const int tid  = threadIdx.x;
    const int lane = tid & 31;
    const int wid  = tid >> 5;
    const int wm   = wid & 1;   // 0..1 -> 64 rows each
    const int wn   = wid >> 1;  // 0..3 -> 32 cols each
    const int bm   = blockIdx.y * BM;
    const int bn   = blockIdx.x * BN;

    float acc[4][4][4];
    #pragma unroll
    for (int i = 0; i < 4; ++i)
        #pragma unroll
        for (int j = 0; j < 4; ++j)
            #pragma unroll
            for (int k = 0; k < 4; ++k) acc[i][j][k] = 0.f;

    uint32_t a[4][4];      // single-buffered A fragments (4 m-tiles)
    uint32_t b[2][2][4];   // double-buffered B fragments (2 n-blocks)

    load_stage(sbase, 0, bm, bn, 0, tid);
    load_stage(sbase, 1, bm, bn, 1, tid);

    #pragma unroll 1
    for (int kt = 0; kt < NKT; ++kt) {
        const int buf = kt % NSTAGE;
        cp_wait<1>();
        __syncthreads();   // single barrier per iteration

        // buffer (kt+2)%3 last read in iter kt-1; barrier above protects it.
        if (kt + 2 < NKT) load_stage(sbase, (kt + 2) % NSTAGE, bm, bn, kt + 2, tid);
        else              cp_commit();  // keep group count aligned for cp_wait<1>

        const uint32_t sA = sbase + (uint32_t)buf * STG_STRIDE;
        const uint32_t sB = sA + 16384u;

        load_b_frags(b[0], sB, 0, lane, wn);

        #pragma unroll
        for (int kk = 0; kk < 4; ++kk) {   // 4 x k16 per BK=64
            const int cur = kk & 1;
            // A fragments for this kk (latency hidden by 16 warps/SM)
            #pragma unroll
            for (int mt = 0; mt < 4; ++mt) {
                int r = wm * 64 + mt * 16 + (lane & 15);
                int c = kk * 2 + (lane >> 4);
                ldsm_x4(a[mt][0], a[mt][1], a[mt][2], a[mt][3],
                        sA + (uint32_t)(((r << 3) | (c ^ (r & 7))) << 4));
            }
            // prefetch next kk's B fragments
            if (kk < 3) load_b_frags(b[cur ^ 1], sB, kk + 1, lane, wn);

            #pragma unroll
            for (int mt = 0; mt < 4; ++mt)
                #pragma unroll
                for (int nt = 0; nt < 4; ++nt)
                    mma16816(acc[mt][nt],
                             a[mt][0], a[mt][1], a[mt][2], a[mt][3],
                             b[cur][nt >> 1][(nt & 1) * 2],
                             b[cur][nt >> 1][(nt & 1) * 2 + 1]);
        }
    }

    // Epilogue: out = -s * sqrt(max(x2 + w2 - 2*cross, eps))
    const float sc = __ldg(scales);
    #pragma unroll
    for (int mt = 0; mt < 4; ++mt) {
        const int row = bm + wm * 64 + mt * 16 + (lane >> 2);
        const float x2a = g_x2[row];
        const float x2b = g_x2[row + 8];
        #pragma unroll
        for (int nt = 0; nt < 4; ++nt) {
            const int col = bn + wn * 32 + nt * 8 + ((lane & 3) << 1);
            if (col < N_DIM) {   // col even, N_DIM even -> col+1 also valid
                const float w2a = g_w2[col];
                const float w2b = g_w2[col + 1];
                float2 v;
                v.x = -sc * sqrtf(fmaxf(x2a + w2a - 2.f * acc[mt][nt][0], EPS_D2));
                v.y = -sc * sqrtf(fmaxf(x2a + w2b - 2.f * acc[mt][nt][1], EPS_D2));
                *reinterpret_cast<float2*>(out + (size_t)row * N_DIM + col) = v;
                v.x = -sc * sqrtf(fmaxf(x2b + w2a - 2.f * acc[mt][nt][2], EPS_D2));
                v.y = -sc * sqrtf(fmaxf(x2b + w2b - 2.f * acc[mt][nt][3], EPS_D2));
                *reinterpret_cast<float2*>(out + (size_t)(row + 8) * N_DIM + col) = v;
            }
        }
    }
}

// ---------------- launch ----------------
extern "C" void kernel_launch(void* const* d_in, const int* in_sizes, int n_in,
                              void* d_out, int out_size) {
    const float* x      = (const float*)d_in[0];  // [16384, 2048]
    const float* w      = (const float*)d_in[1];  // [1000, 2048]
    const float* scales = (const float*)d_in[2];  // [1]
    float* out          = (float*)d_out;          // [16384, 1000]

    convert_x_kernel<<<M_DIM / 8, 256>>>(x);
    convert_w_kernel<<<N_PAD / 8, 256>>>(w);

    cudaFuncSetAttribute(gemm_dist_kernel,
                         cudaFuncAttributeMaxDynamicSharedMemorySize, NSTAGE * STG_STRIDE);
    dim3 grid(N_PAD / BN, M_DIM / BM);  // (8, 128) = 1024 CTAs
    gemm_dist_kernel<<<grid, 256, NSTAGE * STG_STRIDE>>>(scales, out);
}